// round 2
// baseline (speedup 1.0000x reference)
#include <cuda_runtime.h>

// Problem shape (fixed per metadata):
//   X0 [4,1024,256] f32, t [4,1] f32, Wc_w [128,256] f32, Wc_b [128] f32,
//   w [128] f32, A [64,128,6] f32, Bp [64,128,6] f32  ->  out [4,1024,64] f32
#define B_   4
#define S_   1024
#define ROWS 4096        // B_*S_
#define DIN  256
#define Q_   128
#define KF   6
#define DOUT 64

// Scratch (no allocs allowed)
__device__ float g_angle[ROWS * Q_];             // 2 MB
__device__ float g_afold[Q_ * KF * 2 * DOUT];    // 384 KB, [(q*6+k)*2 + {0:sin,1:cos}][d]

// ---- packed fp32 helpers (Blackwell f32x2) --------------------------------
typedef unsigned long long u64;

#define FFMA2(d, a, b) asm("fma.rn.f32x2 %0, %1, %2, %3;" : "=l"(d) : "l"(a), "l"(b), "l"(d))

__device__ __forceinline__ void unpack2(u64 v, float& lo, float& hi) {
    asm("mov.b64 {%0, %1}, %2;" : "=f"(lo), "=f"(hi) : "l"(v));
}

struct u64x2 { u64 x, y; };

// ---------------------------------------------------------------------------
// Kernel 1: fold A,Bp into coefficient matrices for the sin/cos basis
// ---------------------------------------------------------------------------
__global__ void fold_kernel(const float* __restrict__ A, const float* __restrict__ Bp) {
    int i = blockIdx.x * blockDim.x + threadIdx.x;       // over DOUT*Q_*KF = 49152
    if (i >= DOUT * Q_ * KF) return;
    int d   = i / (Q_ * KF);
    int rem = i - d * (Q_ * KF);
    int q   = rem / KF;
    int k   = rem - q * KF;
    float a = A[i], b = Bp[i];
    float sb, cb;
    __sincosf(b, &sb, &cb);           // Bp in [0, 2*pi): fast path is accurate
    int f = (q * KF + k) * 2;
    g_afold[f * DOUT + d]       = a * cb;   // multiplies sin(k*angle)
    g_afold[(f + 1) * DOUT + d] = a * sb;   // multiplies cos(k*angle)
}

// ---------------------------------------------------------------------------
// Kernel 2: angle[row][q] = X0[row,:] . Wc_w[q,:] + Wc_b[q] + w[q]*t[b]
// 64x64 tile, 256 threads, FFMA2 inner loop:
//   A-pairs: consecutive rows packed for free from transposed Xs
//   B: duplicated (w,w) float2 in Ws2 so no per-FMA packing
// ---------------------------------------------------------------------------
__global__ __launch_bounds__(256) void angle_kernel(
    const float* __restrict__ X0, const float* __restrict__ W,
    const float* __restrict__ bias, const float* __restrict__ wvec,
    const float* __restrict__ tvec)
{
    __shared__ __align__(16) float  Xs[32][64];    // [kk][row]      8 KB
    __shared__ __align__(16) float2 Ws2[32][64];   // [kk][q] dup   16 KB

    int tid = threadIdx.x;
    int r0  = blockIdx.x * 64;
    int q0  = blockIdx.y * 64;
    int lr  = tid >> 2;            // 0..63 : row/q being loaded
    int lc  = (tid & 3) * 8;       // 0,8,16,24 : k-offset being loaded
    int rt  = tid & 15;            // rows rt*4 .. rt*4+3
    int ct  = tid >> 4;            // q    ct*4 .. ct*4+3

    u64 acc[2][4] = {};            // [row-pair][q]; lo=even row, hi=odd row

    for (int kb = 0; kb < DIN; kb += 32) {
        float4 xa = *(const float4*)&X0[(r0 + lr) * DIN + kb + lc];
        float4 xb = *(const float4*)&X0[(r0 + lr) * DIN + kb + lc + 4];
        float4 wa = *(const float4*)&W [(q0 + lr) * DIN + kb + lc];
        float4 wb = *(const float4*)&W [(q0 + lr) * DIN + kb + lc + 4];
        __syncthreads();           // previous iteration's reads complete
        Xs[lc+0][lr]=xa.x; Xs[lc+1][lr]=xa.y; Xs[lc+2][lr]=xa.z; Xs[lc+3][lr]=xa.w;
        Xs[lc+4][lr]=xb.x; Xs[lc+5][lr]=xb.y; Xs[lc+6][lr]=xb.z; Xs[lc+7][lr]=xb.w;
        Ws2[lc+0][lr]=make_float2(wa.x,wa.x); Ws2[lc+1][lr]=make_float2(wa.y,wa.y);
        Ws2[lc+2][lr]=make_float2(wa.z,wa.z); Ws2[lc+3][lr]=make_float2(wa.w,wa.w);
        Ws2[lc+4][lr]=make_float2(wb.x,wb.x); Ws2[lc+5][lr]=make_float2(wb.y,wb.y);
        Ws2[lc+6][lr]=make_float2(wb.z,wb.z); Ws2[lc+7][lr]=make_float2(wb.w,wb.w);
        __syncthreads();
        #pragma unroll
        for (int kk = 0; kk < 32; kk++) {
            u64x2 a  = *(const u64x2*)&Xs[kk][rt * 4];        // (r0,r1),(r2,r3)
            u64x2 b0 = *(const u64x2*)&Ws2[kk][ct * 4];       // (q0,q0),(q1,q1)
            u64x2 b1 = *(const u64x2*)(&Ws2[kk][ct * 4] + 2); // (q2,q2),(q3,q3)
            FFMA2(acc[0][0], a.x, b0.x);
            FFMA2(acc[0][1], a.x, b0.y);
            FFMA2(acc[0][2], a.x, b1.x);
            FFMA2(acc[0][3], a.x, b1.y);
            FFMA2(acc[1][0], a.y, b0.x);
            FFMA2(acc[1][1], a.y, b0.y);
            FFMA2(acc[1][2], a.y, b1.x);
            FFMA2(acc[1][3], a.y, b1.y);
        }
    }

    #pragma unroll
    for (int p = 0; p < 2; p++) {
        #pragma unroll
        for (int j = 0; j < 4; j++) {
            float lo, hi;
            unpack2(acc[p][j], lo, hi);
            int qg = q0 + ct * 4 + j;
            float bw = bias[qg];
            float wv = wvec[qg];
            int rgl = r0 + rt * 4 + p * 2;
            g_angle[rgl * Q_ + qg]       = lo + bw + wv * tvec[rgl >> 10];
            g_angle[(rgl + 1) * Q_ + qg] = hi + bw + wv * tvec[(rgl + 1) >> 10];
        }
    }
}

// ---------------------------------------------------------------------------
// Kernel 3: fused feature-gen + GEMM2 with FFMA2.
// Each block: 32 rows. Loop over 32 q-chunks of 4 q's (48 features each):
//   - copy Afold chunk into smem DUPLICATED as (b,b) float2  [48][64]
//   - threads with ql<4 do one (row,q): Cody-Waite reduce, __sincosf,
//     angle-addition recurrence -> 12 features into featT[48][32]
//   - rank-48 FFMA2 update of the V[32][64] tile (1 row-pair x 4 d / thread)
// Next chunk's Afold + angle LDGs are prefetched into registers before the
// GEMM phase so their L2 latency is hidden under the FMA stream.
// ---------------------------------------------------------------------------
__global__ __launch_bounds__(256) void fuse_kernel(float* __restrict__ out)
{
    __shared__ __align__(16) float  featT[48][32];   // [f][row]      6 KB
    __shared__ __align__(16) float2 afs2[48][64];    // [f][d] dup   24 KB

    int tid = threadIdx.x;
    int r0  = blockIdx.x * 32;
    int row = tid & 31;               // feature-gen row
    int ql  = tid >> 5;               // feature-gen local q (only ql<4 active)
    int rt  = tid & 15;               // GEMM row-pair: rows rt*2, rt*2+1
    int ct  = tid >> 4;               // GEMM d group ct*4..ct*4+3

    u64 acc[4] = {};                  // (row-pair) x 4 d

    // prefetch chunk 0
    float4 nv[6];
    {
        const float4* src = (const float4*)(g_afold);
        #pragma unroll
        for (int i = 0; i < 6; i++) nv[i] = src[(tid + 256 * i) >> 1];
    }
    float a_next = (ql < 4) ? g_angle[(r0 + row) * Q_ + ql] : 0.0f;

    for (int qc = 0; qc < 32; qc++) {
        // --- stage Afold chunk duplicated: dst[j2] covers 2 d-values ---
        float4* dst = (float4*)afs2;              // 1536 float4s
        int odd = tid & 1;
        #pragma unroll
        for (int i = 0; i < 6; i++) {
            int j2 = tid + 256 * i;
            float4 v = nv[i];
            float x = odd ? v.z : v.x;
            float y = odd ? v.w : v.y;
            dst[j2] = make_float4(x, x, y, y);
        }

        // --- features for q = qc*4 + ql ---
        if (ql < 4) {
            float a = a_next;
            // 2-term Cody-Waite reduction mod 2*pi (C1 = 6.28125: 9 mantissa
            // bits -> n*C1 exact; subtraction exact by cancellation)
            float n = rintf(a * 0.15915494309189535f);
            float r = fmaf(n, -6.28125f, a);
            r = fmaf(n, -1.9353071795864769e-3f, r);
            float s1, c1;
            __sincosf(r, &s1, &c1);       // |r| <= pi: fast-path accurate
            float sk = s1, ck = c1;
            int base = ql * 12;
            featT[base + 0][row] = sk;
            featT[base + 1][row] = ck;
            #pragma unroll
            for (int k = 1; k < KF; k++) {
                float sn = fmaf(sk, c1, ck * s1);   // sin((k+1)a)
                float cn = fmaf(ck, c1, -sk * s1);  // cos((k+1)a)
                featT[base + 2 * k][row]     = sn;
                featT[base + 2 * k + 1][row] = cn;
                sk = sn; ck = cn;
            }
        }

        // --- prefetch next chunk while this chunk's GEMM runs ---
        if (qc < 31) {
            const float4* src = (const float4*)(g_afold + (qc + 1) * 3072);
            #pragma unroll
            for (int i = 0; i < 6; i++) nv[i] = src[(tid + 256 * i) >> 1];
            if (ql < 4)
                a_next = g_angle[(r0 + row) * Q_ + (qc + 1) * 4 + ql];
        }
        __syncthreads();

        // --- rank-48 FFMA2 update ---
        #pragma unroll 16
        for (int f = 0; f < 48; f++) {
            u64 ap = *(const u64*)&featT[f][rt * 2];            // (row rt*2, rt*2+1)
            u64x2 b0 = *(const u64x2*)&afs2[f][ct * 4];         // (d0,d0),(d1,d1)
            u64x2 b1 = *(const u64x2*)(&afs2[f][ct * 4] + 2);   // (d2,d2),(d3,d3)
            FFMA2(acc[0], ap, b0.x);
            FFMA2(acc[1], ap, b0.y);
            FFMA2(acc[2], ap, b1.x);
            FFMA2(acc[3], ap, b1.y);
        }
        __syncthreads();   // guard next chunk's smem overwrite
    }

    float lo0, hi0, lo1, hi1, lo2, hi2, lo3, hi3;
    unpack2(acc[0], lo0, hi0);
    unpack2(acc[1], lo1, hi1);
    unpack2(acc[2], lo2, hi2);
    unpack2(acc[3], lo3, hi3);
    int rg = r0 + rt * 2;
    *(float4*)&out[rg * DOUT + ct * 4]       = make_float4(lo0, lo1, lo2, lo3);
    *(float4*)&out[(rg + 1) * DOUT + ct * 4] = make_float4(hi0, hi1, hi2, hi3);
}

// ---------------------------------------------------------------------------
extern "C" void kernel_launch(void* const* d_in, const int* in_sizes, int n_in,
                              void* d_out, int out_size) {
    const float* X0   = (const float*)d_in[0];
    const float* tvec = (const float*)d_in[1];
    const float* Wc_w = (const float*)d_in[2];
    const float* Wc_b = (const float*)d_in[3];
    const float* wvec = (const float*)d_in[4];
    const float* A    = (const float*)d_in[5];
    const float* Bp   = (const float*)d_in[6];
    float* out = (float*)d_out;

    fold_kernel<<<(DOUT * Q_ * KF + 255) / 256, 256>>>(A, Bp);
    angle_kernel<<<dim3(ROWS / 64, Q_ / 64), 256>>>(X0, Wc_w, Wc_b, wvec, tvec);
    fuse_kernel<<<ROWS / 32, 256>>>(out);
}

// round 4
// speedup vs baseline: 2.0090x; 2.0090x over previous
#include <cuda_runtime.h>
#include <cuda_fp16.h>
#include <cstdint>

// Problem shape (fixed per metadata):
//   X0 [4,1024,256] f32, t [4,1] f32, Wc_w [128,256] f32, Wc_b [128] f32,
//   w [128] f32, A [64,128,6] f32, Bp [64,128,6] f32  ->  out [4,1024,64] f32
#define B_   4
#define S_   1024
#define ROWS 4096        // B_*S_
#define DIN  256
#define Q_   128
#define KF   6
#define DOUT 64
#define KSLOTS 3072      // 2 fp16 slots per feature, 1536 features

// Scratch (no device allocs allowed)
__device__ float  g_angle[ROWS * Q_];          // 2 MB
__device__ __half g_bh[DOUT * KSLOTS];         // 384 KB, [d][k] row-major fp16

// ---------------------------------------------------------------------------
// m16n8k16 fp16 MMA with fp32 accumulate (legacy tensor-core path, sm_80+)
// ---------------------------------------------------------------------------
__device__ __forceinline__ void mma16816(float* c, const uint32_t* a,
                                         const uint32_t* b) {
    asm volatile(
        "mma.sync.aligned.m16n8k16.row.col.f32.f16.f16.f32 "
        "{%0,%1,%2,%3}, {%4,%5,%6,%7}, {%8,%9}, {%0,%1,%2,%3};"
        : "+f"(c[0]), "+f"(c[1]), "+f"(c[2]), "+f"(c[3])
        : "r"(a[0]), "r"(a[1]), "r"(a[2]), "r"(a[3]), "r"(b[0]), "r"(b[1]));
}

// ---------------------------------------------------------------------------
// Kernel 1: fold A,Bp into fp16 B-operand g_bh[d][k] (coefficient duplicated
// into both K-slots of each feature, matching the (fh,fl) feature split).
//   feature f = q*12 + 2h   -> sin((h+1)a), coeff A*cos(Bp), slots 2f,2f+1
//   feature f = q*12 + 2h+1 -> cos((h+1)a), coeff A*sin(Bp)
// ---------------------------------------------------------------------------
__global__ void fold_kernel(const float* __restrict__ A, const float* __restrict__ Bp) {
    int i = blockIdx.x * blockDim.x + threadIdx.x;       // over DOUT*Q_*KF = 49152
    if (i >= DOUT * Q_ * KF) return;
    int d   = i / (Q_ * KF);
    int rem = i - d * (Q_ * KF);                          // q*6 + h
    float a = A[i], b = Bp[i];
    float sb, cb;
    __sincosf(b, &sb, &cb);
    __half hs = __float2half_rn(a * cb);                  // sin-feature coeff
    __half hc = __float2half_rn(a * sb);                  // cos-feature coeff
    __half2 p0 = __halves2half2(hs, hs);
    __half2 p1 = __halves2half2(hc, hc);
    *(uint2*)&g_bh[d * KSLOTS + rem * 4] =
        make_uint2(*(uint32_t*)&p0, *(uint32_t*)&p1);
}

// ---------------------------------------------------------------------------
// Kernel 2: angle[row][q] = X0[row,:] . Wc_w[q,:] + Wc_b[q] + w[q]*t[b]
// (unchanged known-good fp32 SIMT GEMM)
// ---------------------------------------------------------------------------
__global__ __launch_bounds__(256) void angle_kernel(
    const float* __restrict__ X0, const float* __restrict__ W,
    const float* __restrict__ bias, const float* __restrict__ wvec,
    const float* __restrict__ tvec)
{
    __shared__ float Xs[32][64];   // [kk][row]
    __shared__ float Ws[32][64];   // [kk][q]

    int tid = threadIdx.x;
    int r0  = blockIdx.x * 64;
    int q0  = blockIdx.y * 64;
    int lr  = tid >> 2;
    int lc  = (tid & 3) * 8;
    int rt  = tid & 15;
    int ct  = tid >> 4;

    float acc[4][4] = {};

    for (int kb = 0; kb < DIN; kb += 32) {
        float4 xa = *(const float4*)&X0[(r0 + lr) * DIN + kb + lc];
        float4 xb = *(const float4*)&X0[(r0 + lr) * DIN + kb + lc + 4];
        float4 wa = *(const float4*)&W [(q0 + lr) * DIN + kb + lc];
        float4 wb = *(const float4*)&W [(q0 + lr) * DIN + kb + lc + 4];
        __syncthreads();
        Xs[lc+0][lr]=xa.x; Xs[lc+1][lr]=xa.y; Xs[lc+2][lr]=xa.z; Xs[lc+3][lr]=xa.w;
        Xs[lc+4][lr]=xb.x; Xs[lc+5][lr]=xb.y; Xs[lc+6][lr]=xb.z; Xs[lc+7][lr]=xb.w;
        Ws[lc+0][lr]=wa.x; Ws[lc+1][lr]=wa.y; Ws[lc+2][lr]=wa.z; Ws[lc+3][lr]=wa.w;
        Ws[lc+4][lr]=wb.x; Ws[lc+5][lr]=wb.y; Ws[lc+6][lr]=wb.z; Ws[lc+7][lr]=wb.w;
        __syncthreads();
        #pragma unroll
        for (int kk = 0; kk < 32; kk++) {
            float4 a4 = *(float4*)&Xs[kk][rt * 4];
            float4 b4 = *(float4*)&Ws[kk][ct * 4];
            acc[0][0]=fmaf(a4.x,b4.x,acc[0][0]); acc[0][1]=fmaf(a4.x,b4.y,acc[0][1]);
            acc[0][2]=fmaf(a4.x,b4.z,acc[0][2]); acc[0][3]=fmaf(a4.x,b4.w,acc[0][3]);
            acc[1][0]=fmaf(a4.y,b4.x,acc[1][0]); acc[1][1]=fmaf(a4.y,b4.y,acc[1][1]);
            acc[1][2]=fmaf(a4.y,b4.z,acc[1][2]); acc[1][3]=fmaf(a4.y,b4.w,acc[1][3]);
            acc[2][0]=fmaf(a4.z,b4.x,acc[2][0]); acc[2][1]=fmaf(a4.z,b4.y,acc[2][1]);
            acc[2][2]=fmaf(a4.z,b4.z,acc[2][2]); acc[2][3]=fmaf(a4.z,b4.w,acc[2][3]);
            acc[3][0]=fmaf(a4.w,b4.x,acc[3][0]); acc[3][1]=fmaf(a4.w,b4.y,acc[3][1]);
            acc[3][2]=fmaf(a4.w,b4.z,acc[3][2]); acc[3][3]=fmaf(a4.w,b4.w,acc[3][3]);
        }
    }

    #pragma unroll
    for (int i = 0; i < 4; i++) {
        int rg = r0 + rt * 4 + i;
        float tb = tvec[rg >> 10];
        #pragma unroll
        for (int j = 0; j < 4; j++) {
            int qg = q0 + ct * 4 + j;
            g_angle[rg * Q_ + qg] = acc[i][j] + bias[qg] + wvec[qg] * tb;
        }
    }
}

// ---------------------------------------------------------------------------
// Kernel 3: fused feature-gen + mma.sync fp16-split GEMM.
// 128 CTAs x 128 threads, 32 rows/CTA. 16 chunks of 8 q (192 k-slots).
// smem padded to 200 halves/row (stride 400B) -> conflict-free frag LDS/STS.
// Warp w: 32 rows x 16 d (d cols [w*16, w*16+16)), 2 mtiles x 2 ntiles.
// Pipeline: STS feats+B -> sync -> prefetch LDG (next B, next angle) ->
//           12 ktiles x 4 HMMA -> compute next feats -> sync.
// ---------------------------------------------------------------------------
#define KPAD   200
#define CHUNK_K 192
#define NCHUNK  16

__global__ __launch_bounds__(128) void fuse_kernel(float* __restrict__ out)
{
    __shared__ __half As[32][KPAD];   // 12.8 KB, rows x k
    __shared__ __half Bs[64][KPAD];   // 25.6 KB, d x k

    int tid  = threadIdx.x;
    int lane = tid & 31;
    int w    = tid >> 5;              // warp 0..3
    int r0   = blockIdx.x * 32;
    int row  = lane;                  // featgen row (0..31)
    // thread handles featgen for (row, ql = 2w + p), p = 0,1

    float acc[2][2][4] = {};

    // ---- prologue: prefetch chunk 0 ----
    uint4 nB[12];
    float nAng[2];
    {
        #pragma unroll
        for (int r = 0; r < 12; r++) {
            int idx = tid + 128 * r;
            int d   = idx / 24;
            int kc  = idx - d * 24;
            nB[r] = *(const uint4*)&g_bh[d * KSLOTS + kc * 8];
        }
        #pragma unroll
        for (int p = 0; p < 2; p++)
            nAng[p] = g_angle[(r0 + row) * Q_ + (2 * w + p)];
    }

    for (int c = 0; c < NCHUNK; c++) {
        // ---- compute features for this chunk from nAng ----
        uint4 fr[6];
        #pragma unroll
        for (int p = 0; p < 2; p++) {
            float a = nAng[p];
            // Cody-Waite reduction mod 2*pi (C1=6.28125: 9 mantissa bits)
            float n = rintf(a * 0.15915494309189535f);
            float rr = fmaf(n, -6.28125f, a);
            rr = fmaf(n, -1.9353071795864769e-3f, rr);
            float s1, c1;
            __sincosf(rr, &s1, &c1);
            float f[12];
            f[0] = s1; f[1] = c1;
            float sk = s1, ck = c1;
            #pragma unroll
            for (int h = 1; h < KF; h++) {
                float sn = fmaf(sk, c1, ck * s1);
                float cn = fmaf(ck, c1, -sk * s1);
                f[2 * h] = sn; f[2 * h + 1] = cn;
                sk = sn; ck = cn;
            }
            #pragma unroll
            for (int g = 0; g < 3; g++) {
                uint32_t pr[4];
                #pragma unroll
                for (int jj = 0; jj < 4; jj++) {
                    float v = f[4 * g + jj];
                    __half fh = __float2half_rn(v);
                    __half fl = __float2half_rn(v - __half2float(fh));
                    __half2 h2 = __halves2half2(fh, fl);
                    pr[jj] = *(uint32_t*)&h2;
                }
                fr[3 * p + g] = make_uint4(pr[0], pr[1], pr[2], pr[3]);
            }
        }

        // ---- STS features + B chunk ----
        #pragma unroll
        for (int p = 0; p < 2; p++) {
            int ql = 2 * w + p;
            #pragma unroll
            for (int g = 0; g < 3; g++)
                *(uint4*)&As[row][ql * 24 + 8 * g] = fr[3 * p + g];
        }
        #pragma unroll
        for (int r = 0; r < 12; r++) {
            int idx = tid + 128 * r;
            int d   = idx / 24;
            int kc  = idx - d * 24;
            *(uint4*)&Bs[d][kc * 8] = nB[r];
        }
        __syncthreads();

        // ---- prefetch next chunk (hidden under MMA) ----
        if (c < NCHUNK - 1) {
            #pragma unroll
            for (int r = 0; r < 12; r++) {
                int idx = tid + 128 * r;
                int d   = idx / 24;
                int kc  = idx - d * 24;
                nB[r] = *(const uint4*)&g_bh[d * KSLOTS + (c + 1) * CHUNK_K + kc * 8];
            }
            #pragma unroll
            for (int p = 0; p < 2; p++)
                nAng[p] = g_angle[(r0 + row) * Q_ + (c + 1) * 8 + (2 * w + p)];
        }

        // ---- MMA: 12 ktiles x (2m x 2n) ----
        int ra = lane >> 2;
        int cc = 2 * (lane & 3);
        #pragma unroll
        for (int kt = 0; kt < 12; kt++) {
            int k0 = kt * 16 + cc;
            uint32_t A0[4], A1[4], Bf0[2], Bf1[2];
            A0[0] = *(const uint32_t*)&As[ra][k0];
            A0[1] = *(const uint32_t*)&As[ra + 8][k0];
            A0[2] = *(const uint32_t*)&As[ra][k0 + 8];
            A0[3] = *(const uint32_t*)&As[ra + 8][k0 + 8];
            A1[0] = *(const uint32_t*)&As[ra + 16][k0];
            A1[1] = *(const uint32_t*)&As[ra + 24][k0];
            A1[2] = *(const uint32_t*)&As[ra + 16][k0 + 8];
            A1[3] = *(const uint32_t*)&As[ra + 24][k0 + 8];
            int d0 = w * 16 + ra;
            Bf0[0] = *(const uint32_t*)&Bs[d0][k0];
            Bf0[1] = *(const uint32_t*)&Bs[d0][k0 + 8];
            Bf1[0] = *(const uint32_t*)&Bs[d0 + 8][k0];
            Bf1[1] = *(const uint32_t*)&Bs[d0 + 8][k0 + 8];
            mma16816(acc[0][0], A0, Bf0);
            mma16816(acc[0][1], A0, Bf1);
            mma16816(acc[1][0], A1, Bf0);
            mma16816(acc[1][1], A1, Bf1);
        }
        __syncthreads();
    }

    // ---- epilogue ----
    int orow = r0 + (lane >> 2);
    int ocol = w * 16 + 2 * (lane & 3);
    #pragma unroll
    for (int m = 0; m < 2; m++) {
        #pragma unroll
        for (int nt = 0; nt < 2; nt++) {
            float* a4 = acc[m][nt];
            int rr = orow + m * 16;
            int ccg = ocol + nt * 8;
            *(float2*)&out[rr * DOUT + ccg]       = make_float2(a4[0], a4[1]);
            *(float2*)&out[(rr + 8) * DOUT + ccg] = make_float2(a4[2], a4[3]);
        }
    }
}

// ---------------------------------------------------------------------------
extern "C" void kernel_launch(void* const* d_in, const int* in_sizes, int n_in,
                              void* d_out, int out_size) {
    const float* X0   = (const float*)d_in[0];
    const float* tvec = (const float*)d_in[1];
    const float* Wc_w = (const float*)d_in[2];
    const float* Wc_b = (const float*)d_in[3];
    const float* wvec = (const float*)d_in[4];
    const float* A    = (const float*)d_in[5];
    const float* Bp   = (const float*)d_in[6];
    float* out = (float*)d_out;

    fold_kernel<<<(DOUT * Q_ * KF + 255) / 256, 256>>>(A, Bp);
    angle_kernel<<<dim3(ROWS / 64, Q_ / 64), 256>>>(X0, Wc_w, Wc_b, wvec, tvec);
    fuse_kernel<<<ROWS / 32, 128>>>(out);
}

// round 5
// speedup vs baseline: 3.3077x; 1.6464x over previous
#include <cuda_runtime.h>
#include <cuda_fp16.h>
#include <cstdint>

// Problem shape (fixed per metadata):
//   X0 [4,1024,256] f32, t [4,1] f32, Wc_w [128,256] f32, Wc_b [128] f32,
//   w [128] f32, A [64,128,6] f32, Bp [64,128,6] f32  ->  out [4,1024,64] f32
#define B_   4
#define S_   1024
#define ROWS 4096        // B_*S_
#define DIN  256
#define Q_   128
#define KF   6
#define DOUT 64
#define KSL  1536        // 1 fp16 slot per feature now
#define WKS  768         // 3 fp16 slots per W element (xh*wh + xh*wl + xl*wh)

// Scratch (no device allocs allowed)
__device__ float  g_angle[ROWS * Q_];          // 2 MB
__device__ __half g_bh[DOUT * KSL];            // 192 KB, [d][k] fp16 coeffs
__device__ __half g_wsp[Q_ * WKS];             // 192 KB, W split triplets

// ---------------------------------------------------------------------------
// m16n8k16 fp16 MMA with fp32 accumulate (sm_80+ baseline path)
// ---------------------------------------------------------------------------
__device__ __forceinline__ void mma16816(float* c, const uint32_t* a,
                                         const uint32_t* b) {
    asm volatile(
        "mma.sync.aligned.m16n8k16.row.col.f32.f16.f16.f32 "
        "{%0,%1,%2,%3}, {%4,%5,%6,%7}, {%8,%9}, {%0,%1,%2,%3};"
        : "+f"(c[0]), "+f"(c[1]), "+f"(c[2]), "+f"(c[3])
        : "r"(a[0]), "r"(a[1]), "r"(a[2]), "r"(a[3]), "r"(b[0]), "r"(b[1]));
}

// ---------------------------------------------------------------------------
// Kernel 1 (prep): fold A,Bp -> fp16 coeff matrix g_bh; split W -> g_wsp.
//   coeff slot q*12 + 2h   : A*cos(Bp)  (multiplies sin((h+1)a))
//   coeff slot q*12 + 2h+1 : A*sin(Bp)  (multiplies cos((h+1)a))
//   W triplet at 3k: [wh, wl, wh] with w = wh + wl (exact fp16 split)
// ---------------------------------------------------------------------------
__global__ void prep_kernel(const float* __restrict__ A, const float* __restrict__ Bp,
                            const float* __restrict__ W) {
    int i = blockIdx.x * blockDim.x + threadIdx.x;       // 0 .. 49151
    if (i < DOUT * Q_ * KF) {
        int d   = i / (Q_ * KF);
        int rem = i - d * (Q_ * KF);                     // q*6 + h
        float a = A[i], b = Bp[i];
        float sb, cb;
        __sincosf(b, &sb, &cb);
        __half2 hv = __floats2half2_rn(a * cb, a * sb);
        *(uint32_t*)&g_bh[d * KSL + rem * 2] = *(uint32_t*)&hv;
    }
    if (i < Q_ * DIN) {                                  // 32768 W elements
        float w = W[i];
        __half wh = __float2half_rn(w);
        __half wl = __float2half_rn(w - __half2float(wh));
        int q = i >> 8, k = i & 255;
        __half* p = &g_wsp[q * WKS + 3 * k];
        p[0] = wh; p[1] = wl; p[2] = wh;
    }
}

// ---------------------------------------------------------------------------
// Kernel 2: angle = X0 @ Wc_w^T + bias + w*t  via HMMA with 3-product split.
// 128 CTAs x 128 threads; CTA = 32 rows x 128 q; K = 256 f32 -> 768 slots,
// 8 chunks of 32 f32 (96 slots). X0 split in-kernel; W pre-split (g_wsp).
// smem: Ax[32][104], Ws[128][104] halves (33.2 KB), stride 208B ->
// conflict-free fragment LDS (bank = 20*r + c, distinct over a warp).
// ---------------------------------------------------------------------------
#define KP2 104

__global__ __launch_bounds__(128) void angle_kernel(
    const float* __restrict__ X0, const float* __restrict__ bias,
    const float* __restrict__ wvec, const float* __restrict__ tvec)
{
    __shared__ __half Ax[32][KP2];    //  6.6 KB
    __shared__ __half Ws[128][KP2];   // 26.6 KB

    int tid  = threadIdx.x;
    int lane = tid & 31;
    int w    = tid >> 5;              // warp 0..3, q range w*32..w*32+31
    int r0   = blockIdx.x * 32;

    int xrow = tid >> 2;              // 0..31
    int kgrp = (tid & 3) * 8;         // f32 k offset within chunk

    float acc[2][4][4] = {};          // [mtile][ntile][frag]

    // prologue prefetch: chunk 0
    float4 nx0 = *(const float4*)&X0[(r0 + xrow) * DIN + kgrp];
    float4 nx1 = *(const float4*)&X0[(r0 + xrow) * DIN + kgrp + 4];
    uint4 nW[12];
    #pragma unroll
    for (int r = 0; r < 12; r++) {
        int idx = tid + 128 * r;      // 0..1535
        int q   = idx / 12;
        int kc  = idx - q * 12;
        nW[r] = *(const uint4*)&g_wsp[q * WKS + kc * 8];
    }

    for (int c = 0; c < 8; c++) {
        // ---- convert 8 f32 -> 24 halves (xh,xh,xl triplets), 3 STS.128 ----
        {
            float xf[8] = {nx0.x, nx0.y, nx0.z, nx0.w, nx1.x, nx1.y, nx1.z, nx1.w};
            uint32_t hv[12];
            #pragma unroll
            for (int j = 0; j < 8; j += 4) {
                __half h0 = __float2half_rn(xf[j]);
                __half l0 = __float2half_rn(xf[j] - __half2float(h0));
                __half h1 = __float2half_rn(xf[j + 1]);
                __half l1 = __float2half_rn(xf[j + 1] - __half2float(h1));
                __half h2 = __float2half_rn(xf[j + 2]);
                __half l2 = __float2half_rn(xf[j + 2] - __half2float(h2));
                __half h3 = __float2half_rn(xf[j + 3]);
                __half l3 = __float2half_rn(xf[j + 3] - __half2float(h3));
                int o = (j >> 2) * 6;
                __half2 t0 = __halves2half2(h0, h0);
                __half2 t1 = __halves2half2(l0, h1);
                __half2 t2 = __halves2half2(h1, l1);
                __half2 t3 = __halves2half2(h2, h2);
                __half2 t4 = __halves2half2(l2, h3);
                __half2 t5 = __halves2half2(h3, l3);
                hv[o+0]=*(uint32_t*)&t0; hv[o+1]=*(uint32_t*)&t1; hv[o+2]=*(uint32_t*)&t2;
                hv[o+3]=*(uint32_t*)&t3; hv[o+4]=*(uint32_t*)&t4; hv[o+5]=*(uint32_t*)&t5;
            }
            uint4* dst = (uint4*)&Ax[xrow][3 * kgrp];
            dst[0] = make_uint4(hv[0], hv[1], hv[2], hv[3]);
            dst[1] = make_uint4(hv[4], hv[5], hv[6], hv[7]);
            dst[2] = make_uint4(hv[8], hv[9], hv[10], hv[11]);
        }
        // ---- stage W chunk ----
        #pragma unroll
        for (int r = 0; r < 12; r++) {
            int idx = tid + 128 * r;
            int q   = idx / 12;
            int kc  = idx - q * 12;
            *(uint4*)&Ws[q][kc * 8] = nW[r];
        }
        __syncthreads();

        // ---- prefetch next chunk (hidden under MMA) ----
        if (c < 7) {
            nx0 = *(const float4*)&X0[(r0 + xrow) * DIN + (c + 1) * 32 + kgrp];
            nx1 = *(const float4*)&X0[(r0 + xrow) * DIN + (c + 1) * 32 + kgrp + 4];
            #pragma unroll
            for (int r = 0; r < 12; r++) {
                int idx = tid + 128 * r;
                int q   = idx / 12;
                int kc  = idx - q * 12;
                nW[r] = *(const uint4*)&g_wsp[q * WKS + (c + 1) * 96 + kc * 8];
            }
        }

        // ---- MMA: 6 ktiles x (2 mtiles x 4 ntiles) ----
        int ra = lane >> 2;
        int cc = 2 * (lane & 3);
        #pragma unroll
        for (int kt = 0; kt < 6; kt++) {
            int k0 = kt * 16 + cc;
            uint32_t A0[4], A1[4];
            A0[0] = *(const uint32_t*)&Ax[ra][k0];
            A0[1] = *(const uint32_t*)&Ax[ra + 8][k0];
            A0[2] = *(const uint32_t*)&Ax[ra][k0 + 8];
            A0[3] = *(const uint32_t*)&Ax[ra + 8][k0 + 8];
            A1[0] = *(const uint32_t*)&Ax[ra + 16][k0];
            A1[1] = *(const uint32_t*)&Ax[ra + 24][k0];
            A1[2] = *(const uint32_t*)&Ax[ra + 16][k0 + 8];
            A1[3] = *(const uint32_t*)&Ax[ra + 24][k0 + 8];
            #pragma unroll
            for (int n = 0; n < 4; n++) {
                int q0 = w * 32 + n * 8 + ra;
                uint32_t Bf[2];
                Bf[0] = *(const uint32_t*)&Ws[q0][k0];
                Bf[1] = *(const uint32_t*)&Ws[q0][k0 + 8];
                mma16816(acc[0][n], A0, Bf);
                mma16816(acc[1][n], A1, Bf);
            }
        }
        __syncthreads();
    }

    // ---- epilogue: + bias + w*t, STG ----
    float tb = tvec[r0 >> 10];        // whole CTA in one batch (32 | 1024)
    int ra = lane >> 2;
    int cc = 2 * (lane & 3);
    #pragma unroll
    for (int n = 0; n < 4; n++) {
        int q = w * 32 + n * 8 + cc;
        float b0 = bias[q] + wvec[q] * tb;
        float b1 = bias[q + 1] + wvec[q + 1] * tb;
        #pragma unroll
        for (int m = 0; m < 2; m++) {
            int rr = r0 + m * 16 + ra;
            float* a4 = acc[m][n];
            *(float2*)&g_angle[rr * Q_ + q]       = make_float2(a4[0] + b0, a4[1] + b1);
            *(float2*)&g_angle[(rr + 8) * Q_ + q] = make_float2(a4[2] + b0, a4[3] + b1);
        }
    }
}

// ---------------------------------------------------------------------------
// Kernel 3: fused feature-gen + HMMA GEMM2 (K=1536, single-fp16 features).
// 128 CTAs x 128 threads, 32 rows/CTA. 8 chunks of 16 q (192 k-slots).
// Thread (t): featgen rows t&31, q = chunk*16 + (t>>5)*4 .. +3 (float4 angle
// load). Warp w GEMM tile: 32 rows x 16 d. smem stride 400B (conflict-free).
// ---------------------------------------------------------------------------
#define KPAD   200
#define CHUNK_K 192
#define NCHUNK  8

__global__ __launch_bounds__(128) void fuse_kernel(float* __restrict__ out)
{
    __shared__ __half As[32][KPAD];   // 12.8 KB
    __shared__ __half Bs[64][KPAD];   // 25.6 KB

    int tid  = threadIdx.x;
    int lane = tid & 31;
    int w    = tid >> 5;
    int r0   = blockIdx.x * 32;
    int row  = lane;                  // featgen row
    int qlb  = w * 4;                 // featgen local-q base (4 q per thread)

    float acc[2][2][4] = {};

    // prologue prefetch: chunk 0
    uint4 nB[12];
    #pragma unroll
    for (int r = 0; r < 12; r++) {
        int idx = tid + 128 * r;
        int d   = idx / 24;
        int kc  = idx - d * 24;
        nB[r] = *(const uint4*)&g_bh[d * KSL + kc * 8];
    }
    float4 nAng = *(const float4*)&g_angle[(r0 + row) * Q_ + qlb];

    for (int c = 0; c < NCHUNK; c++) {
        // ---- features for 4 q's -> fp16, STS ----
        {
            float af[4] = {nAng.x, nAng.y, nAng.z, nAng.w};
            #pragma unroll
            for (int p = 0; p < 4; p++) {
                float a = af[p];
                // Cody-Waite reduction mod 2*pi (C1=6.28125: 9 mantissa bits)
                float n = rintf(a * 0.15915494309189535f);
                float rr = fmaf(n, -6.28125f, a);
                rr = fmaf(n, -1.9353071795864769e-3f, rr);
                float s1, c1;
                __sincosf(rr, &s1, &c1);
                float f[12];
                f[0] = s1; f[1] = c1;
                float sk = s1, ck = c1;
                #pragma unroll
                for (int h = 1; h < KF; h++) {
                    float sn = fmaf(sk, c1, ck * s1);
                    float cn = fmaf(ck, c1, -sk * s1);
                    f[2 * h] = sn; f[2 * h + 1] = cn;
                    sk = sn; ck = cn;
                }
                uint32_t hv[6];
                #pragma unroll
                for (int g = 0; g < 6; g++) {
                    __half2 h2 = __floats2half2_rn(f[2 * g], f[2 * g + 1]);
                    hv[g] = *(uint32_t*)&h2;
                }
                int kl = (qlb + p) * 12;
                uint64_t* dst = (uint64_t*)&As[row][kl];
                dst[0] = (uint64_t)hv[0] | ((uint64_t)hv[1] << 32);
                dst[1] = (uint64_t)hv[2] | ((uint64_t)hv[3] << 32);
                dst[2] = (uint64_t)hv[4] | ((uint64_t)hv[5] << 32);
            }
        }
        // ---- stage B chunk ----
        #pragma unroll
        for (int r = 0; r < 12; r++) {
            int idx = tid + 128 * r;
            int d   = idx / 24;
            int kc  = idx - d * 24;
            *(uint4*)&Bs[d][kc * 8] = nB[r];
        }
        __syncthreads();

        // ---- prefetch next chunk ----
        if (c < NCHUNK - 1) {
            #pragma unroll
            for (int r = 0; r < 12; r++) {
                int idx = tid + 128 * r;
                int d   = idx / 24;
                int kc  = idx - d * 24;
                nB[r] = *(const uint4*)&g_bh[d * KSL + (c + 1) * CHUNK_K + kc * 8];
            }
            nAng = *(const float4*)&g_angle[(r0 + row) * Q_ + (c + 1) * 16 + qlb];
        }

        // ---- MMA: 12 ktiles x (2m x 2n) ----
        int ra = lane >> 2;
        int cc = 2 * (lane & 3);
        #pragma unroll
        for (int kt = 0; kt < 12; kt++) {
            int k0 = kt * 16 + cc;
            uint32_t A0[4], A1[4], Bf0[2], Bf1[2];
            A0[0] = *(const uint32_t*)&As[ra][k0];
            A0[1] = *(const uint32_t*)&As[ra + 8][k0];
            A0[2] = *(const uint32_t*)&As[ra][k0 + 8];
            A0[3] = *(const uint32_t*)&As[ra + 8][k0 + 8];
            A1[0] = *(const uint32_t*)&As[ra + 16][k0];
            A1[1] = *(const uint32_t*)&As[ra + 24][k0];
            A1[2] = *(const uint32_t*)&As[ra + 16][k0 + 8];
            A1[3] = *(const uint32_t*)&As[ra + 24][k0 + 8];
            int d0 = w * 16 + ra;
            Bf0[0] = *(const uint32_t*)&Bs[d0][k0];
            Bf0[1] = *(const uint32_t*)&Bs[d0][k0 + 8];
            Bf1[0] = *(const uint32_t*)&Bs[d0 + 8][k0];
            Bf1[1] = *(const uint32_t*)&Bs[d0 + 8][k0 + 8];
            mma16816(acc[0][0], A0, Bf0);
            mma16816(acc[0][1], A0, Bf1);
            mma16816(acc[1][0], A1, Bf0);
            mma16816(acc[1][1], A1, Bf1);
        }
        __syncthreads();
    }

    // ---- epilogue ----
    int orow = r0 + (lane >> 2);
    int ocol = w * 16 + 2 * (lane & 3);
    #pragma unroll
    for (int m = 0; m < 2; m++) {
        #pragma unroll
        for (int nt = 0; nt < 2; nt++) {
            float* a4 = acc[m][nt];
            int rr  = orow + m * 16;
            int ccg = ocol + nt * 8;
            *(float2*)&out[rr * DOUT + ccg]       = make_float2(a4[0], a4[1]);
            *(float2*)&out[(rr + 8) * DOUT + ccg] = make_float2(a4[2], a4[3]);
        }
    }
}

// ---------------------------------------------------------------------------
extern "C" void kernel_launch(void* const* d_in, const int* in_sizes, int n_in,
                              void* d_out, int out_size) {
    const float* X0   = (const float*)d_in[0];
    const float* tvec = (const float*)d_in[1];
    const float* Wc_w = (const float*)d_in[2];
    const float* Wc_b = (const float*)d_in[3];
    const float* wvec = (const float*)d_in[4];
    const float* A    = (const float*)d_in[5];
    const float* Bp   = (const float*)d_in[6];
    float* out = (float*)d_out;

    prep_kernel<<<(DOUT * Q_ * KF + 255) / 256, 256>>>(A, Bp, Wc_w);
    angle_kernel<<<ROWS / 32, 128>>>(X0, Wc_b, wvec, tvec);
    fuse_kernel<<<ROWS / 32, 128>>>(out);
}